// round 5
// baseline (speedup 1.0000x reference)
#include <cuda_runtime.h>
#include <cuda_bf16.h>

// Problem constants
#define BATCH 256
#define TT    1024
#define INP   128
#define LAT   64
#define HID   128
#define OUTD  32

// Scratch: drive[b][t][l] (fp32), 64 MB
__device__ float g_drive[(size_t)BATCH * TT * LAT];

// ---------- f32x2 helpers ----------
__device__ __forceinline__ void fma2(unsigned long long& acc,
                                     unsigned long long a,
                                     unsigned long long b) {
    asm("fma.rn.f32x2 %0, %1, %2, %0;" : "+l"(acc) : "l"(a), "l"(b));
}
__device__ __forceinline__ float psum2(unsigned long long v) {
    float lo, hi;
    asm("mov.b64 {%0,%1}, %2;" : "=f"(lo), "=f"(hi) : "l"(v));
    return lo + hi;
}
__device__ __forceinline__ void gbar(int id) {
    asm volatile("bar.sync %0, 256;" :: "r"(id) : "memory");
}

// =====================================================================
// Kernel 1: drive = input @ C^T      [B*T,128] x [64,128]^T -> [B*T,64]
// =====================================================================
__global__ void __launch_bounds__(256, 1)
drive_kernel(const float* __restrict__ inp, const float* __restrict__ Cg) {
    extern __shared__ char smem1[];
    float*  As = reinterpret_cast<float*>(smem1);                  // [128][132]
    float4* Cq = reinterpret_cast<float4*>(smem1 + 128 * 132 * 4); // [32][64]

    const int tid = threadIdx.x;
    const int m0  = blockIdx.x * 128;

    #pragma unroll
    for (int e = tid; e < 4096; e += 256) {
        int row = e >> 5;
        int c4  = e & 31;
        float4 v = reinterpret_cast<const float4*>(inp + (size_t)(m0 + row) * INP)[c4];
        *reinterpret_cast<float4*>(&As[row * 132 + c4 * 4]) = v;
    }
    #pragma unroll
    for (int idx = tid; idx < 2048; idx += 256) {
        Cq[(idx & 31) * 64 + (idx >> 5)] = reinterpret_cast<const float4*>(Cg)[idx];
    }
    __syncthreads();

    const int ctx = tid & 15;
    const int rty = tid >> 4;

    unsigned long long acc[8][4];
    #pragma unroll
    for (int r = 0; r < 8; ++r)
        #pragma unroll
        for (int c = 0; c < 4; ++c) acc[r][c] = 0ull;

    #pragma unroll 4
    for (int jq = 0; jq < 32; ++jq) {
        ulonglong2 cw[4];
        #pragma unroll
        for (int c = 0; c < 4; ++c)
            cw[c] = *reinterpret_cast<const ulonglong2*>(&Cq[jq * 64 + ctx + 16 * c]);
        #pragma unroll
        for (int r = 0; r < 8; ++r) {
            ulonglong2 av =
                *reinterpret_cast<const ulonglong2*>(&As[(rty * 8 + r) * 132 + 4 * jq]);
            #pragma unroll
            for (int c = 0; c < 4; ++c) {
                fma2(acc[r][c], av.x, cw[c].x);
                fma2(acc[r][c], av.y, cw[c].y);
            }
        }
    }

    #pragma unroll
    for (int r = 0; r < 8; ++r) {
        size_t row = (size_t)(m0 + rty * 8 + r);
        #pragma unroll
        for (int c = 0; c < 4; ++c)
            g_drive[row * LAT + ctx + 16 * c] = psum2(acc[r][c]);
    }
}

// =====================================================================
// Kernel 2: scan. 128 blocks x 512 threads = 2 chains of 256 threads.
// 16 warps/SM = 4 per SMSP (latency hiding). Per-lane weights = 64 regs
// (k-split x2 in phase1, x4 in phase2; butterfly shfl reductions).
// 2 named barriers per step, hidden by 4 resident warps/SMSP.
// =====================================================================
__global__ void __launch_bounds__(512, 1)
recur_kernel(const float* __restrict__ Ag,   const float* __restrict__ W1g,
             const float* __restrict__ W2g,  const float* __restrict__ h1g,
             const float* __restrict__ h2g,  const float* __restrict__ Woutg,
             const float* __restrict__ boutg, float* __restrict__ outg) {
    __shared__ __align__(16) float zsg[2][LAT];
    __shared__ __align__(16) float hidg[2][HID];

    const int tid = threadIdx.x;
    const int gid = tid >> 8;          // chain (batch) within block
    const int ct  = tid & 255;         // thread within chain
    const int bat = blockIdx.x * 2 + gid;
    const int barid = 1 + gid;

    // phase1 mapping: h = ct>>1 (hidden row), kp = ct&1 (k-half of z)
    const int h  = ct >> 1;
    const int kp = ct & 1;
    // phase2 mapping: l = ct>>2 (z row), ks = ct&3 (k-quarter of hidden)
    const int l  = ct >> 2;
    const int ks = ct & 3;

    // register-resident weights (16 + 16 u64 = 64 regs)
    unsigned long long w2r[16];
    #pragma unroll
    for (int j = 0; j < 16; ++j)
        w2r[j] = *reinterpret_cast<const unsigned long long*>(
            &W2g[h * LAT + kp * 32 + 2 * j]);
    unsigned long long w1r[16];
    #pragma unroll
    for (int j = 0; j < 16; ++j)
        w1r[j] = *reinterpret_cast<const unsigned long long*>(
            &W1g[l * HID + ks * 32 + 2 * j]);

    const float h2h = h2g[h];
    const float Al  = Ag[l];
    const float h1l = h1g[l];

    if (ct < LAT) zsg[gid][ct] = 0.0f;
    __syncthreads();

    const float* zrow = &zsg[gid][kp * 32];   // 32-float k-chunk for phase1
    const float* hrow = &hidg[gid][ks * 32];  // 32-float k-chunk for phase2

    float zcur = 0.0f;                        // z[l], redundant in 4 lanes
    const size_t ubase = ((size_t)bat) * TT * LAT + l;
    float u_cur = g_drive[ubase];
    float u_nxt = g_drive[ubase + LAT];

    const unsigned FULL = 0xffffffffu;

    for (int t = 0; t < TT; ++t) {
        const int tp = (t + 2 < TT) ? (t + 2) : (TT - 1);
        float u_fut = g_drive[ubase + (size_t)tp * LAT];

        // ---- phase 1: hidden[h] = relu( z . W2[h] + h2[h] ), k-split x2
        {
            unsigned long long a0 = 0, a1 = 0;
            #pragma unroll
            for (int i = 0; i < 4; ++i) {
                ulonglong2 q0 = *reinterpret_cast<const ulonglong2*>(&zrow[8 * i]);
                ulonglong2 q1 = *reinterpret_cast<const ulonglong2*>(&zrow[8 * i + 4]);
                fma2(a0, q0.x, w2r[4 * i]);
                fma2(a1, q0.y, w2r[4 * i + 1]);
                fma2(a0, q1.x, w2r[4 * i + 2]);
                fma2(a1, q1.y, w2r[4 * i + 3]);
            }
            float s = psum2(a0) + psum2(a1);
            s += __shfl_xor_sync(FULL, s, 1);          // butterfly: both k-halves
            if (!kp) hidg[gid][h] = fmaxf(s + h2h, 0.0f);
        }
        gbar(barid);

        // ---- phase 2: z'[l] = clip(z*A + hidden . W1[l] + h1 + u), k-split x4
        {
            unsigned long long p0 = 0, p1 = 0;
            #pragma unroll
            for (int i = 0; i < 4; ++i) {
                ulonglong2 q0 = *reinterpret_cast<const ulonglong2*>(&hrow[8 * i]);
                ulonglong2 q1 = *reinterpret_cast<const ulonglong2*>(&hrow[8 * i + 4]);
                fma2(p0, q0.x, w1r[4 * i]);
                fma2(p1, q0.y, w1r[4 * i + 1]);
                fma2(p0, q1.x, w1r[4 * i + 2]);
                fma2(p1, q1.y, w1r[4 * i + 3]);
            }
            float d = psum2(p0) + psum2(p1);
            d += __shfl_xor_sync(FULL, d, 1);          // butterfly over 4 k-lanes
            d += __shfl_xor_sync(FULL, d, 2);

            float zn = zcur * Al + d + h1l + u_cur;
            zn = fminf(5.0f, fmaxf(-5.0f, zn));
            zcur = zn;
            if (ks == 0) zsg[gid][l] = zn;             // one writer per element
        }
        u_cur = u_nxt;
        u_nxt = u_fut;
        gbar(barid);
    }

    // ---- epilogue: out[bat][o] = zT . Wout[o] + bout[o]
    if (ct < OUTD) {
        const int o = ct;
        float acc = boutg[o];
        #pragma unroll
        for (int ll = 0; ll < LAT; ++ll) acc += zsg[gid][ll] * Woutg[o * LAT + ll];
        outg[(size_t)bat * OUTD + o] = acc;
    }
}

// =====================================================================
extern "C" void kernel_launch(void* const* d_in, const int* in_sizes, int n_in,
                              void* d_out, int out_size) {
    (void)in_sizes; (void)n_in; (void)out_size;
    const float* inp   = (const float*)d_in[0];
    const float* Ag    = (const float*)d_in[1];
    const float* W1g   = (const float*)d_in[2];
    const float* W2g   = (const float*)d_in[3];
    const float* h1g   = (const float*)d_in[4];
    const float* h2g   = (const float*)d_in[5];
    const float* Cg    = (const float*)d_in[6];
    const float* Woutg = (const float*)d_in[7];
    const float* boutg = (const float*)d_in[8];
    float* outg = (float*)d_out;

    const int smem1 = 128 * 132 * 4 + 32 * 64 * 16; // 100352 B
    cudaFuncSetAttribute(drive_kernel, cudaFuncAttributeMaxDynamicSharedMemorySize, smem1);

    drive_kernel<<<(BATCH * TT) / 128, 256, smem1>>>(inp, Cg);
    recur_kernel<<<BATCH / 2, 512>>>(Ag, W1g, W2g, h1g, h2g, Woutg, boutg, outg);
}

// round 6
// speedup vs baseline: 2.5865x; 2.5865x over previous
#include <cuda_runtime.h>
#include <cuda_bf16.h>

// Problem constants
#define BATCH 256
#define TT    1024
#define INP   128
#define LAT   64
#define HID   128
#define OUTD  32

// Scratch: drive[b][t][l] (fp32), 64 MB
__device__ float g_drive[(size_t)BATCH * TT * LAT];

// ---------- f32x2 helpers ----------
__device__ __forceinline__ void fma2(unsigned long long& acc,
                                     unsigned long long a,
                                     unsigned long long b) {
    asm("fma.rn.f32x2 %0, %1, %2, %0;" : "+l"(acc) : "l"(a), "l"(b));
}
__device__ __forceinline__ float psum2(unsigned long long v) {
    float lo, hi;
    asm("mov.b64 {%0,%1}, %2;" : "=f"(lo), "=f"(hi) : "l"(v));
    return lo + hi;
}
__device__ __forceinline__ void gbar(int id) {
    asm volatile("bar.sync %0, 256;" :: "r"(id) : "memory");
}

// =====================================================================
// Kernel 1: drive = input @ C^T      [B*T,128] x [64,128]^T -> [B*T,64]
// =====================================================================
__global__ void __launch_bounds__(256, 1)
drive_kernel(const float* __restrict__ inp, const float* __restrict__ Cg) {
    extern __shared__ char smem1[];
    float*  As = reinterpret_cast<float*>(smem1);                  // [128][132]
    float4* Cq = reinterpret_cast<float4*>(smem1 + 128 * 132 * 4); // [32][64]

    const int tid = threadIdx.x;
    const int m0  = blockIdx.x * 128;

    #pragma unroll
    for (int e = tid; e < 4096; e += 256) {
        int row = e >> 5;
        int c4  = e & 31;
        float4 v = reinterpret_cast<const float4*>(inp + (size_t)(m0 + row) * INP)[c4];
        *reinterpret_cast<float4*>(&As[row * 132 + c4 * 4]) = v;
    }
    #pragma unroll
    for (int idx = tid; idx < 2048; idx += 256) {
        Cq[(idx & 31) * 64 + (idx >> 5)] = reinterpret_cast<const float4*>(Cg)[idx];
    }
    __syncthreads();

    const int ctx = tid & 15;
    const int rty = tid >> 4;

    unsigned long long acc[8][4];
    #pragma unroll
    for (int r = 0; r < 8; ++r)
        #pragma unroll
        for (int c = 0; c < 4; ++c) acc[r][c] = 0ull;

    #pragma unroll 4
    for (int jq = 0; jq < 32; ++jq) {
        ulonglong2 cw[4];
        #pragma unroll
        for (int c = 0; c < 4; ++c)
            cw[c] = *reinterpret_cast<const ulonglong2*>(&Cq[jq * 64 + ctx + 16 * c]);
        #pragma unroll
        for (int r = 0; r < 8; ++r) {
            ulonglong2 av =
                *reinterpret_cast<const ulonglong2*>(&As[(rty * 8 + r) * 132 + 4 * jq]);
            #pragma unroll
            for (int c = 0; c < 4; ++c) {
                fma2(acc[r][c], av.x, cw[c].x);
                fma2(acc[r][c], av.y, cw[c].y);
            }
        }
    }

    #pragma unroll
    for (int r = 0; r < 8; ++r) {
        size_t row = (size_t)(m0 + rty * 8 + r);
        #pragma unroll
        for (int c = 0; c < 4; ++c)
            g_drive[row * LAT + ctx + 16 * c] = psum2(acc[r][c]);
    }
}

// =====================================================================
// Kernel 2: scan. 128 blocks x 512 threads = 2 chains of 256 threads.
// Conflict-free pad-swizzled smem (36-float chunk stride). Per lane:
// phase1 = 4 rows x 8k (2 LDS.128), phase2 = 2 rows x 16k (4 LDS.128).
// Reduce-scatter shfl trees. 64 weight regs/lane -> 16 warps/SM.
// =====================================================================
#define ZSTRIDE 36   // 8-float chunks, chunk k at float offset 36k
#define HSTRIDE 36   // 16-float chunks, chunk k at float offset 36k

__global__ void __launch_bounds__(512, 1)
recur_kernel(const float* __restrict__ Ag,   const float* __restrict__ W1g,
             const float* __restrict__ W2g,  const float* __restrict__ h1g,
             const float* __restrict__ h2g,  const float* __restrict__ Woutg,
             const float* __restrict__ boutg, float* __restrict__ outg) {
    __shared__ __align__(16) float zbuf[2][8 * ZSTRIDE];   // z, padded chunks
    __shared__ __align__(16) float hbuf[2][8 * HSTRIDE];   // hidden, padded chunks

    const int tid = threadIdx.x;
    const int gid = tid >> 8;          // chain (batch) within block
    const int c   = tid & 255;         // lane index within chain
    const int bat = blockIdx.x * 2 + gid;
    const int barid = 1 + gid;

    // ---- phase1 mapping: kc1 = k-chunk (8 floats), rows 4*rg1..+3
    const int kc1 = c & 7;
    const int rg1 = c >> 3;            // 0..31
    const int b4a = (c >> 2) & 1;
    const int b2a = (c >> 1) & 1;
    const int hrow = 4 * rg1 + 2 * b4a + b2a;   // hidden row this lane finalizes

    // ---- phase2 mapping: kc2 = k-chunk (16 floats), rows 2*rg2, 2*rg2+1
    const int kc2 = c & 7;
    const int rg2 = c >> 3;            // 0..31
    const int b4b = (c >> 2) & 1;
    const int lz  = 2 * rg2 + b4b;     // z row this lane finalizes (wait: rg2 in 0..31 -> rows 0..63)

    // register-resident weights: 16 + 16 u64 = 64 regs
    unsigned long long w2r[4][4];      // [row r][k-pair j]
    #pragma unroll
    for (int r = 0; r < 4; ++r)
        #pragma unroll
        for (int j = 0; j < 4; ++j)
            w2r[r][j] = *reinterpret_cast<const unsigned long long*>(
                &W2g[(4 * rg1 + r) * LAT + 8 * kc1 + 2 * j]);
    unsigned long long w1r[2][8];
    #pragma unroll
    for (int r = 0; r < 2; ++r)
        #pragma unroll
        for (int j = 0; j < 8; ++j)
            w1r[r][j] = *reinterpret_cast<const unsigned long long*>(
                &W1g[(2 * rg2 + r) * HID + 16 * kc2 + 2 * j]);

    const float h2c = h2g[hrow];
    const float Ac  = Ag[lz];
    const float h1c = h1g[lz];

    // init: zero the z slots this chain reads
    if (!(c & 3)) zbuf[gid][(lz >> 3) * ZSTRIDE + (lz & 7)] = 0.0f;
    __syncthreads();

    const float* zptr = &zbuf[gid][kc1 * ZSTRIDE];
    const float* hptr = &hbuf[gid][kc2 * HSTRIDE];

    float zprev = 0.0f;                 // z[lz] (4 redundant lanes)
    const size_t ubase = ((size_t)bat) * TT * LAT + lz;
    float u_cur = g_drive[ubase];
    float u_nxt = g_drive[ubase + LAT];

    const unsigned FULL = 0xffffffffu;

    for (int t = 0; t < TT; ++t) {
        const int tp = (t + 2 < TT) ? (t + 2) : (TT - 1);
        float u_fut = g_drive[ubase + (size_t)tp * LAT];

        // ======== phase 1: hidden = relu(z @ W2^T + h2) ========
        {
            ulonglong2 za = *reinterpret_cast<const ulonglong2*>(zptr);
            ulonglong2 zb = *reinterpret_cast<const ulonglong2*>(zptr + 4);
            float p[4];
            #pragma unroll
            for (int r = 0; r < 4; ++r) {
                unsigned long long acc = 0ull;
                fma2(acc, za.x, w2r[r][0]);
                fma2(acc, za.y, w2r[r][1]);
                fma2(acc, zb.x, w2r[r][2]);
                fma2(acc, zb.y, w2r[r][3]);
                p[r] = psum2(acc);
            }
            // reduce-scatter over 8 kc1 lanes
            float s0 = b4a ? p[0] : p[2];
            float r0 = __shfl_xor_sync(FULL, s0, 4);
            float s1 = b4a ? p[1] : p[3];
            float r1 = __shfl_xor_sync(FULL, s1, 4);
            float q0 = (b4a ? p[2] : p[0]) + r0;   // row 4rg1+2b4
            float q1 = (b4a ? p[3] : p[1]) + r1;   // row 4rg1+2b4+1
            float s2 = b2a ? q0 : q1;
            float r2 = __shfl_xor_sync(FULL, s2, 2);
            float s  = (b2a ? q1 : q0) + r2;       // row hrow
            s += __shfl_xor_sync(FULL, s, 1);
            float hval = fmaxf(s + h2c, 0.0f);
            if (!(c & 1))
                hbuf[gid][(hrow >> 4) * HSTRIDE + (hrow & 15)] = hval;
        }
        gbar(barid);

        // ======== phase 2: z' = clip(z*A + hidden @ W1^T + h1 + u) ========
        {
            ulonglong2 h0 = *reinterpret_cast<const ulonglong2*>(hptr);
            ulonglong2 h1v = *reinterpret_cast<const ulonglong2*>(hptr + 4);
            ulonglong2 h2v = *reinterpret_cast<const ulonglong2*>(hptr + 8);
            ulonglong2 h3v = *reinterpret_cast<const ulonglong2*>(hptr + 12);
            float p0, p1;
            {
                unsigned long long acc = 0ull;
                fma2(acc, h0.x, w1r[0][0]); fma2(acc, h0.y, w1r[0][1]);
                fma2(acc, h1v.x, w1r[0][2]); fma2(acc, h1v.y, w1r[0][3]);
                fma2(acc, h2v.x, w1r[0][4]); fma2(acc, h2v.y, w1r[0][5]);
                fma2(acc, h3v.x, w1r[0][6]); fma2(acc, h3v.y, w1r[0][7]);
                p0 = psum2(acc);
            }
            {
                unsigned long long acc = 0ull;
                fma2(acc, h0.x, w1r[1][0]); fma2(acc, h0.y, w1r[1][1]);
                fma2(acc, h1v.x, w1r[1][2]); fma2(acc, h1v.y, w1r[1][3]);
                fma2(acc, h2v.x, w1r[1][4]); fma2(acc, h2v.y, w1r[1][5]);
                fma2(acc, h3v.x, w1r[1][6]); fma2(acc, h3v.y, w1r[1][7]);
                p1 = psum2(acc);
            }
            // reduce-scatter over 8 kc2 lanes
            float s0 = b4b ? p0 : p1;
            float r0 = __shfl_xor_sync(FULL, s0, 4);
            float s  = (b4b ? p1 : p0) + r0;       // row lz
            s += __shfl_xor_sync(FULL, s, 2);
            s += __shfl_xor_sync(FULL, s, 1);

            float zn = zprev * Ac + s + h1c + u_cur;
            zn = fminf(5.0f, fmaxf(-5.0f, zn));
            zprev = zn;
            if (!(c & 3))
                zbuf[gid][(lz >> 3) * ZSTRIDE + (lz & 7)] = zn;
        }
        u_cur = u_nxt;
        u_nxt = u_fut;
        gbar(barid);
    }

    // ---- epilogue: out[bat][o] = zT . Wout[o] + bout[o]
    if (c < OUTD) {
        const int o = c;
        float acc = boutg[o];
        #pragma unroll
        for (int l = 0; l < LAT; ++l)
            acc += zbuf[gid][(l >> 3) * ZSTRIDE + (l & 7)] * Woutg[o * LAT + l];
        outg[(size_t)bat * OUTD + o] = acc;
    }
}

// =====================================================================
extern "C" void kernel_launch(void* const* d_in, const int* in_sizes, int n_in,
                              void* d_out, int out_size) {
    (void)in_sizes; (void)n_in; (void)out_size;
    const float* inp   = (const float*)d_in[0];
    const float* Ag    = (const float*)d_in[1];
    const float* W1g   = (const float*)d_in[2];
    const float* W2g   = (const float*)d_in[3];
    const float* h1g   = (const float*)d_in[4];
    const float* h2g   = (const float*)d_in[5];
    const float* Cg    = (const float*)d_in[6];
    const float* Woutg = (const float*)d_in[7];
    const float* boutg = (const float*)d_in[8];
    float* outg = (float*)d_out;

    const int smem1 = 128 * 132 * 4 + 32 * 64 * 16; // 100352 B
    cudaFuncSetAttribute(drive_kernel, cudaFuncAttributeMaxDynamicSharedMemorySize, smem1);

    drive_kernel<<<(BATCH * TT) / 128, 256, smem1>>>(inp, Cg);
    recur_kernel<<<BATCH / 2, 512>>>(Ag, W1g, W2g, h1g, h2g, Woutg, boutg, outg);
}

// round 7
// speedup vs baseline: 2.6607x; 1.0287x over previous
#include <cuda_runtime.h>
#include <cuda_bf16.h>

// Problem constants
#define BATCH 256
#define TT    1024
#define INP   128
#define LAT   64
#define HID   128
#define OUTD  32

// Scratch: drive[b][t][l] (fp32), 64 MB
__device__ float g_drive[(size_t)BATCH * TT * LAT];

// ---------- f32x2 helpers ----------
__device__ __forceinline__ void fma2(unsigned long long& acc,
                                     unsigned long long a,
                                     unsigned long long b) {
    asm("fma.rn.f32x2 %0, %1, %2, %0;" : "+l"(acc) : "l"(a), "l"(b));
}
__device__ __forceinline__ float psum2(unsigned long long v) {
    float lo, hi;
    asm("mov.b64 {%0,%1}, %2;" : "=f"(lo), "=f"(hi) : "l"(v));
    return lo + hi;
}
__device__ __forceinline__ void gbar(int id) {
    asm volatile("bar.sync %0, 256;" :: "r"(id) : "memory");
}

// =====================================================================
// Kernel 1: drive = input @ C^T      [B*T,128] x [64,128]^T -> [B*T,64]
// launch_bounds(256,2): cap regs at 128 -> 2 blocks/SM (4 warps/SMSP)
// =====================================================================
__global__ void __launch_bounds__(256, 2)
drive_kernel(const float* __restrict__ inp, const float* __restrict__ Cg) {
    extern __shared__ char smem1[];
    float*  As = reinterpret_cast<float*>(smem1);                  // [128][132]
    float4* Cq = reinterpret_cast<float4*>(smem1 + 128 * 132 * 4); // [32][64]

    const int tid = threadIdx.x;
    const int m0  = blockIdx.x * 128;

    #pragma unroll
    for (int e = tid; e < 4096; e += 256) {
        int row = e >> 5;
        int c4  = e & 31;
        float4 v = reinterpret_cast<const float4*>(inp + (size_t)(m0 + row) * INP)[c4];
        *reinterpret_cast<float4*>(&As[row * 132 + c4 * 4]) = v;
    }
    #pragma unroll
    for (int idx = tid; idx < 2048; idx += 256) {
        Cq[(idx & 31) * 64 + (idx >> 5)] = reinterpret_cast<const float4*>(Cg)[idx];
    }
    __syncthreads();

    const int ctx = tid & 15;
    const int rty = tid >> 4;

    unsigned long long acc[8][4];
    #pragma unroll
    for (int r = 0; r < 8; ++r)
        #pragma unroll
        for (int c = 0; c < 4; ++c) acc[r][c] = 0ull;

    #pragma unroll 4
    for (int jq = 0; jq < 32; ++jq) {
        ulonglong2 cw[4];
        #pragma unroll
        for (int c = 0; c < 4; ++c)
            cw[c] = *reinterpret_cast<const ulonglong2*>(&Cq[jq * 64 + ctx + 16 * c]);
        #pragma unroll
        for (int r = 0; r < 8; ++r) {
            ulonglong2 av =
                *reinterpret_cast<const ulonglong2*>(&As[(rty * 8 + r) * 132 + 4 * jq]);
            #pragma unroll
            for (int c = 0; c < 4; ++c) {
                fma2(acc[r][c], av.x, cw[c].x);
                fma2(acc[r][c], av.y, cw[c].y);
            }
        }
    }

    #pragma unroll
    for (int r = 0; r < 8; ++r) {
        size_t row = (size_t)(m0 + rty * 8 + r);
        #pragma unroll
        for (int c = 0; c < 4; ++c)
            g_drive[row * LAT + ctx + 16 * c] = psum2(acc[r][c]);
    }
}

// =====================================================================
// Kernel 2: scan. 128 blocks x 512 threads = 2 chains of 256 threads.
// phase1: 4 rows x 8k (2 LDS.128, zbuf stride 36 -> conflict-free)
// phase2: 4 rows x 8k (4 LDS.64, hbuf stride 18 -> conflict-free)
// Reduce-scatter shfl trees. 64 weight regs/lane -> 16 warps/SM.
// =====================================================================
#define ZST 36   // z: 8 chunks of 8 floats, chunk k at offset 36k (banks 4k: distinct)
#define HST 18   // hidden: 16 chunks of 8 floats, chunk k at offset 18k (banks 18k mod 32: distinct)

__global__ void __launch_bounds__(512, 1)
recur_kernel(const float* __restrict__ Ag,   const float* __restrict__ W1g,
             const float* __restrict__ W2g,  const float* __restrict__ h1g,
             const float* __restrict__ h2g,  const float* __restrict__ Woutg,
             const float* __restrict__ boutg, float* __restrict__ outg) {
    __shared__ __align__(16) float zbuf[2][8 * ZST];    // z, padded chunks
    __shared__ __align__(16) float hbuf[2][16 * HST];   // hidden, padded chunks

    const int tid = threadIdx.x;
    const int gid = tid >> 8;          // chain (batch) within block
    const int c   = tid & 255;         // lane index within chain
    const int bat = blockIdx.x * 2 + gid;
    const int barid = 1 + gid;

    // ---- phase1 mapping: kc1 = z-chunk (8 floats), rows 4*rg1..+3 of W2
    const int kc1 = c & 7;
    const int rg1 = c >> 3;            // 0..31
    const int b4a = (c >> 2) & 1;
    const int b2a = (c >> 1) & 1;
    const int hrow = 4 * rg1 + 2 * b4a + b2a;   // hidden row this lane finalizes

    // ---- phase2 mapping: kc2 = hidden-chunk (8 floats), rows 4*rg2..+3 of W1
    const int kc2 = c & 15;
    const int rg2 = c >> 4;            // 0..15
    const int b1b = c & 1;
    const int b2b = (c >> 1) & 1;
    const int lz  = 4 * rg2 + 2 * b1b + b2b;    // z row this lane finalizes

    // register-resident weights: 16 + 16 u64 = 64 regs
    unsigned long long w2r[4][4];      // [row r][k-pair j] over chunk kc1
    #pragma unroll
    for (int r = 0; r < 4; ++r)
        #pragma unroll
        for (int j = 0; j < 4; ++j)
            w2r[r][j] = *reinterpret_cast<const unsigned long long*>(
                &W2g[(4 * rg1 + r) * LAT + 8 * kc1 + 2 * j]);
    unsigned long long w1r[4][4];      // [row r][k-pair j] over chunk kc2
    #pragma unroll
    for (int r = 0; r < 4; ++r)
        #pragma unroll
        for (int j = 0; j < 4; ++j)
            w1r[r][j] = *reinterpret_cast<const unsigned long long*>(
                &W1g[(4 * rg2 + r) * HID + 8 * kc2 + 2 * j]);

    const float h2c = h2g[hrow];
    const float Ac  = Ag[lz];
    const float h1c = h1g[lz];

    // init: zero the z slots this chain reads
    if ((c & 12) == 0) zbuf[gid][(lz >> 3) * ZST + (lz & 7)] = 0.0f;
    __syncthreads();

    const float* zptr = &zbuf[gid][kc1 * ZST];
    const unsigned long long* hptr =
        reinterpret_cast<const unsigned long long*>(&hbuf[gid][kc2 * HST]);

    float zprev = 0.0f;                 // z[lz] (4 redundant lanes)
    const size_t ubase = ((size_t)bat) * TT * LAT + lz;
    float u_cur = g_drive[ubase];
    float u_nxt = g_drive[ubase + LAT];

    const unsigned FULL = 0xffffffffu;

    for (int t = 0; t < TT; ++t) {
        const int tp = (t + 2 < TT) ? (t + 2) : (TT - 1);
        float u_fut = g_drive[ubase + (size_t)tp * LAT];

        // ======== phase 1: hidden = relu(z @ W2^T + h2) ========
        {
            ulonglong2 za = *reinterpret_cast<const ulonglong2*>(zptr);
            ulonglong2 zb = *reinterpret_cast<const ulonglong2*>(zptr + 4);
            float p[4];
            #pragma unroll
            for (int r = 0; r < 4; ++r) {
                unsigned long long acc = 0ull;
                fma2(acc, za.x, w2r[r][0]);
                fma2(acc, za.y, w2r[r][1]);
                fma2(acc, zb.x, w2r[r][2]);
                fma2(acc, zb.y, w2r[r][3]);
                p[r] = psum2(acc);
            }
            // reduce-scatter over 8 kc1 lanes (xor4, xor2, xor1)
            float s0 = b4a ? p[0] : p[2];
            float r0 = __shfl_xor_sync(FULL, s0, 4);
            float s1 = b4a ? p[1] : p[3];
            float r1 = __shfl_xor_sync(FULL, s1, 4);
            float q0 = (b4a ? p[2] : p[0]) + r0;   // row 4rg1+2b4a
            float q1 = (b4a ? p[3] : p[1]) + r1;   // row 4rg1+2b4a+1
            float s2 = b2a ? q0 : q1;
            float r2 = __shfl_xor_sync(FULL, s2, 2);
            float s  = (b2a ? q1 : q0) + r2;       // row hrow (half-sum)
            s += __shfl_xor_sync(FULL, s, 1);
            float hval = fmaxf(s + h2c, 0.0f);
            if (!(c & 1))
                hbuf[gid][(hrow >> 3) * HST + (hrow & 7)] = hval;
        }
        gbar(barid);

        // ======== phase 2: z' = clip(z*A + hidden @ W1^T + h1 + u) ========
        {
            unsigned long long h0 = hptr[0];
            unsigned long long h1v = hptr[1];
            unsigned long long h2v = hptr[2];
            unsigned long long h3v = hptr[3];
            float p[4];
            #pragma unroll
            for (int r = 0; r < 4; ++r) {
                unsigned long long acc = 0ull;
                fma2(acc, h0,  w1r[r][0]);
                fma2(acc, h1v, w1r[r][1]);
                fma2(acc, h2v, w1r[r][2]);
                fma2(acc, h3v, w1r[r][3]);
                p[r] = psum2(acc);
            }
            // reduce-scatter over 16 kc2 lanes (xor1, xor2, xor4, xor8)
            float s0 = b1b ? p[0] : p[2];
            float r0 = __shfl_xor_sync(FULL, s0, 1);
            float s1 = b1b ? p[1] : p[3];
            float r1 = __shfl_xor_sync(FULL, s1, 1);
            float q0 = (b1b ? p[2] : p[0]) + r0;   // row 4rg2+2b1b
            float q1 = (b1b ? p[3] : p[1]) + r1;   // row 4rg2+2b1b+1
            float s2 = b2b ? q0 : q1;
            float r2 = __shfl_xor_sync(FULL, s2, 2);
            float v  = (b2b ? q1 : q0) + r2;       // row lz (quarter-sum)
            v += __shfl_xor_sync(FULL, v, 4);
            v += __shfl_xor_sync(FULL, v, 8);      // full sum over 16 kc lanes

            float zn = zprev * Ac + v + h1c + u_cur;
            zn = fminf(5.0f, fmaxf(-5.0f, zn));
            zprev = zn;
            if ((c & 12) == 0)
                zbuf[gid][(lz >> 3) * ZST + (lz & 7)] = zn;
        }
        u_cur = u_nxt;
        u_nxt = u_fut;
        gbar(barid);
    }

    // ---- epilogue: out[bat][o] = zT . Wout[o] + bout[o]
    if (c < OUTD) {
        const int o = c;
        float acc = boutg[o];
        #pragma unroll
        for (int l = 0; l < LAT; ++l)
            acc += zbuf[gid][(l >> 3) * ZST + (l & 7)] * Woutg[o * LAT + l];
        outg[(size_t)bat * OUTD + o] = acc;
    }
}

// =====================================================================
extern "C" void kernel_launch(void* const* d_in, const int* in_sizes, int n_in,
                              void* d_out, int out_size) {
    (void)in_sizes; (void)n_in; (void)out_size;
    const float* inp   = (const float*)d_in[0];
    const float* Ag    = (const float*)d_in[1];
    const float* W1g   = (const float*)d_in[2];
    const float* W2g   = (const float*)d_in[3];
    const float* h1g   = (const float*)d_in[4];
    const float* h2g   = (const float*)d_in[5];
    const float* Cg    = (const float*)d_in[6];
    const float* Woutg = (const float*)d_in[7];
    const float* boutg = (const float*)d_in[8];
    float* outg = (float*)d_out;

    const int smem1 = 128 * 132 * 4 + 32 * 64 * 16; // 100352 B
    cudaFuncSetAttribute(drive_kernel, cudaFuncAttributeMaxDynamicSharedMemorySize, smem1);

    drive_kernel<<<(BATCH * TT) / 128, 256, smem1>>>(inp, Cg);
    recur_kernel<<<BATCH / 2, 512>>>(Ag, W1g, W2g, h1g, h2g, Woutg, boutg, outg);
}